// round 12
// baseline (speedup 1.0000x reference)
#include <cuda_runtime.h>
#include <stdint.h>

// Problem geometry (x: (32, 7, 512, 512) fp32; per-(B,C) slice quantile over H*W)
#define MAX_SLICES 224
#define N_PER      262144           // 512*512
#define M_SAMP     4096
#define NGROUP     512              // sample groups of 8 contiguous floats
#define CAND_MAX   32768

// Sample-rank brackets among 4096 sorted samples.
#define R_LO 100
#define R_HI 3995

#define NBIN 4096                   // top-12 bits of monotone key

// work partition: lagged interleave of gather/normalize tickets
#define GBLK   32                   // gather chunks per slice
#define GCHUNK (N_PER / GBLK)       // 8192 elements
#define NBLKN  32                   // normalize chunks per slice
#define NCHUNK (N_PER / NBLKN)      // 8192 elements
#define TPS    (GBLK + NBLKN)       // 64
#define LAG    40                   // slices of lag between gather and normalize
#define STASH  10                   // per-thread stash (mean ~1.6 of 32 elems)
#define SROW   (STASH + 1)          // padded row, conflict-free
#define OVF    512                  // per-block overflow fallback

// ---- static device scratch (no allocations allowed) ----
__device__ float    g_win[MAX_SLICES][2];    // w1 (lo edge), w2 (hi edge)
__device__ float    g_thr[MAX_SLICES];       // symmetric threshold t (or -1)
__device__ unsigned g_ncand[MAX_SLICES][2];
__device__ float    g_cand[MAX_SLICES][2][CAND_MAX];
__device__ float    g_q[MAX_SLICES][2];
__device__ unsigned g_ticket;
__device__ unsigned g_done[MAX_SLICES];
__device__ unsigned g_flag[MAX_SLICES];

// Monotone float <-> uint key
__device__ __forceinline__ unsigned fkey(float f) {
    unsigned u = __float_as_uint(f);
    return (u & 0x80000000u) ? ~u : (u | 0x80000000u);
}
__device__ __forceinline__ float funkey(unsigned k) {
    return (k & 0x80000000u) ? __uint_as_float(k & 0x7FFFFFFFu)
                             : __uint_as_float(~k);
}
__device__ __forceinline__ unsigned poll_u32(const unsigned* p) {
    unsigned v;
    asm volatile("ld.global.cg.u32 %0, [%1];" : "=r"(v) : "l"(p) : "memory");
    return v;
}

// ============================================================
// Kernel 1: per-slice sample histogram -> tail thresholds
// ============================================================
__global__ void sample_kernel(const float* __restrict__ x) {
    __shared__ unsigned hist[NBIN];
    __shared__ unsigned toff[257];
    __shared__ unsigned sh_bin[2];
    __shared__ unsigned wsum[8];

    int slice = blockIdx.x;
    int tid = threadIdx.x;
    const float* xs = x + (size_t)slice * N_PER;

    if (slice == 0 && tid == 0) g_ticket = 0;

    for (int i = tid; i < NBIN; i += 256) hist[i] = 0;
    __syncthreads();

    #pragma unroll
    for (int g = tid; g < NGROUP; g += 256) {
        const float4* gp = (const float4*)(xs + (size_t)g * (N_PER / NGROUP));
        #pragma unroll
        for (int j = 0; j < 2; j++) {
            float4 v = gp[j];
            atomicAdd(&hist[fkey(v.x) >> 20], 1u);
            atomicAdd(&hist[fkey(v.y) >> 20], 1u);
            atomicAdd(&hist[fkey(v.z) >> 20], 1u);
            atomicAdd(&hist[fkey(v.w) >> 20], 1u);
        }
    }
    __syncthreads();

    unsigned s = 0;
    #pragma unroll
    for (int b = 0; b < 16; b++) s += hist[tid * 16 + b];

    int lane = tid & 31, wrp = tid >> 5;
    unsigned cum = s;
    #pragma unroll
    for (int o = 1; o < 32; o <<= 1) {
        unsigned t = __shfl_up_sync(0xffffffffu, cum, o);
        if (lane >= o) cum += t;
    }
    if (lane == 31) wsum[wrp] = cum;
    __syncthreads();
    if (tid == 0) {
        unsigned acc = 0;
        #pragma unroll
        for (int w = 0; w < 8; w++) { unsigned t = wsum[w]; wsum[w] = acc; acc += t; }
    }
    __syncthreads();
    toff[tid] = wsum[wrp] + cum - s;
    if (tid == 255) toff[256] = M_SAMP;
    __syncthreads();

    const int ranks[2] = {R_LO, R_HI};
    if (tid < 2) {
        unsigned R = (unsigned)ranks[tid];
        int lo = 0, hi = 256;
        while (hi - lo > 1) {
            int mid = (lo + hi) >> 1;
            if (toff[mid] <= R) lo = mid; else hi = mid;
        }
        unsigned acc = toff[lo];
        int bin = lo * 16;
        #pragma unroll
        for (int b = 0; b < 16; b++) {
            unsigned h = hist[lo * 16 + b];
            if (acc + h > R) { bin = lo * 16 + b; break; }
            acc += h;
        }
        sh_bin[tid] = (unsigned)bin;
    }
    __syncthreads();

    if (tid == 0) {
        float w1 = funkey((sh_bin[0] + 1u) << 20);   // upper edge of lo-tail bin
        float w2 = funkey(sh_bin[1] << 20);          // lower edge of hi-tail bin
        g_win[slice][0] = w1;
        g_win[slice][1] = w2;
        // symmetric fast path valid iff w1 < 0 < w2
        g_thr[slice] = (w1 < 0.0f && w2 > 0.0f) ? fminf(-w1, w2) : -1.0f;
        g_ncand[slice][0] = 0; g_ncand[slice][1] = 0;
        g_done[slice] = 0;
        g_flag[slice] = 0;
    }
}

// ============================================================
// Inline select: exact radix-select among candidates of (slice, w).
// w=0: stash contains ALL f below its threshold  -> base count 0.
// w=1: stash contains ALL f >= its threshold     -> base = N - n.
// ============================================================
__device__ void do_select(int slice, int w, unsigned* hist, unsigned* tsum,
                          unsigned* red_u, volatile unsigned* sh2) {
    int tid = threadIdx.x;
    unsigned n_raw = g_ncand[slice][w];
    unsigned n = n_raw > CAND_MAX ? CAND_MAX : n_raw;
    unsigned cnt = (w == 0) ? 0u : (unsigned)N_PER - n_raw;

    double pos  = (w == 0) ? 0.01 * (double)(N_PER - 1) : 0.99 * (double)(N_PER - 1);
    long long K = (long long)pos;
    double frac = pos - (double)K;

    if (n < 2) {
        if (tid == 0) g_q[slice][w] = (n == 1) ? g_cand[slice][w][0] : 0.0f;
        return;
    }
    long long rl = K - (long long)cnt;
    if (rl < 0) rl = 0;
    if (rl > (long long)n - 2) rl = (long long)n - 2;
    int r = (int)rl;
    const float* cand = g_cand[slice][w];

    unsigned prefix = 0, pmask = 0;
    int rrem = r;
    const int shifts[3] = {21, 10, 0};
    const int bitsv[3]  = {11, 11, 10};
    #pragma unroll
    for (int p = 0; p < 3; p++) {
        int shift = shifts[p];
        unsigned nb = 1u << bitsv[p];
        unsigned dmask = nb - 1u;
        unsigned per = nb / 256;
        for (unsigned i = tid; i < 2048; i += 256) hist[i] = 0;
        __syncthreads();
        for (unsigned i = tid; i < n; i += 256) {
            unsigned u = fkey(cand[i]);
            if ((u & pmask) == prefix)
                atomicAdd(&hist[(u >> shift) & dmask], 1u);
        }
        __syncthreads();
        unsigned s = 0;
        for (unsigned q2 = 0; q2 < per; q2++) s += hist[tid * per + q2];
        tsum[tid] = s;
        __syncthreads();

        if (tid < 32) {
            unsigned part[8];
            unsigned ls = 0;
            #pragma unroll
            for (int j = 0; j < 8; j++) { part[j] = tsum[tid * 8 + j]; ls += part[j]; }
            unsigned cum = ls;
            #pragma unroll
            for (int o = 1; o < 32; o <<= 1) {
                unsigned t = __shfl_up_sync(0xffffffffu, cum, o);
                if (tid >= o) cum += t;
            }
            unsigned excl = cum - ls;
            unsigned ball = __ballot_sync(0xffffffffu, cum > (unsigned)rrem);
            int cross = __ffs(ball) - 1;
            if (tid == cross) {
                unsigned acc = excl;
                int tc = tid * 8;
                #pragma unroll
                for (int j = 0; j < 8; j++) {
                    if (acc + part[j] > (unsigned)rrem) { tc = tid * 8 + j; break; }
                    acc += part[j];
                }
                unsigned d = (unsigned)tc * per;
                for (unsigned b = 0; b < per; b++) {
                    unsigned h = hist[tc * per + b];
                    if (acc + h > (unsigned)rrem) { d = (unsigned)tc * per + b; break; }
                    acc += h;
                }
                sh2[0] = d;
                sh2[1] = (unsigned)rrem - acc;
            }
        }
        __syncthreads();
        prefix |= sh2[0] << shift;
        pmask  |= dmask << shift;
        rrem = (int)sh2[1];
        __syncthreads();
    }
    unsigned v0key = prefix;

    unsigned cle = 0, mgt = 0xFFFFFFFFu;
    for (unsigned i = tid; i < n; i += 256) {
        unsigned u = fkey(cand[i]);
        cle += (u <= v0key);
        if (u > v0key && u < mgt) mgt = u;
    }
    red_u[tid] = cle; __syncthreads();
    for (int o = 128; o; o >>= 1) {
        if (tid < o) red_u[tid] += red_u[tid + o];
        __syncthreads();
    }
    unsigned cle_tot = red_u[0]; __syncthreads();
    red_u[tid] = mgt; __syncthreads();
    for (int o = 128; o; o >>= 1) {
        if (tid < o) red_u[tid] = (red_u[tid + o] < red_u[tid]) ? red_u[tid + o] : red_u[tid];
        __syncthreads();
    }
    unsigned mgt_tot = red_u[0];
    __syncthreads();

    if (tid == 0) {
        unsigned v1key = (cle_tot >= (unsigned)(r + 2)) ? v0key
                       : ((mgt_tot != 0xFFFFFFFFu) ? mgt_tot : v0key);
        double v0 = (double)funkey(v0key);
        double v1 = (double)funkey(v1key);
        g_q[slice][w] = (float)(v0 + frac * (v1 - v0));
    }
}

// ============================================================
// Mega kernel: lagged-interleave ticket schedule.
//   tickets [0, lag*32):              gather slices [0, lag)
//   then per group k in [0, S-lag):   32 gather (slice lag+k)
//                                     then 32 normalize (slice k)
//   tail:                             normalize slices [S-lag, S)
// Normalize of slice k runs ~2 waves after its gather finished
// (no spinning) and ~80 MB of stream distance behind it
// (still L2-resident -> second read of x hits L2, not DRAM).
// ============================================================
__global__ void __launch_bounds__(256) mega_kernel(const float* __restrict__ x,
                                                   float* __restrict__ out) {
    __shared__ float stL[256 * SROW];        // 11.3 KB
    __shared__ float stH[256 * SROW];        // 11.3 KB (aliased in select)
    __shared__ float ovfL[OVF], ovfH[OVF];   // 4 KB
    __shared__ unsigned s_u[16];
    __shared__ unsigned wsumL[8], wsumH[8];
    __shared__ float s_q[2];

    int tid = threadIdx.x;
    int lane = tid & 31, wrp = tid >> 5;
    int slices = gridDim.x / TPS;
    int lag = slices < LAG ? slices : LAG;

    if (tid == 0) {
        s_u[0] = atomicAdd(&g_ticket, 1u);
        s_u[1] = 0; s_u[2] = 0;
    }
    __syncthreads();
    unsigned ticket = s_u[0];

    // ---- decode ticket -> (is_gather, slice, part) ----
    unsigned G0  = (unsigned)(lag * GBLK);
    unsigned MID = (unsigned)((slices - lag) * TPS);
    int is_gather, slice, part;
    if (ticket < G0) {
        is_gather = 1; slice = (int)(ticket / GBLK); part = (int)(ticket % GBLK);
    } else if (ticket < G0 + MID) {
        unsigned t = ticket - G0;
        unsigned grp = t / TPS, r = t % TPS;
        if (r < GBLK) { is_gather = 1; slice = lag + (int)grp; part = (int)r; }
        else          { is_gather = 0; slice = (int)grp; part = (int)(r - GBLK); }
    } else {
        unsigned t = ticket - G0 - MID;
        is_gather = 0; slice = (slices - lag) + (int)(t / NBLKN); part = (int)(t % NBLKN);
    }

    if (is_gather) {
        // ---------------- gather role ----------------
        const float4* xs = (const float4*)(x + (size_t)slice * N_PER
                                             + (size_t)part * GCHUNK);
        float thr = g_thr[slice];

        float* pL = &stL[tid * SROW];
        float* pH = &stH[tid * SROW];
        unsigned nl = 0, nh = 0;

        if (thr >= 0.0f) {
            // symmetric fast path: 4x FSETP(|f|,t) OR-folded, one branch/float4
            #pragma unroll
            for (int kb = 0; kb < 2; kb++) {
                float4 r[4];
                #pragma unroll
                for (int k = 0; k < 4; k++)
                    r[k] = xs[tid + (kb * 4 + k) * 256];
                #pragma unroll
                for (int k = 0; k < 4; k++) {
                    float4 v = r[k];
                    bool any = (fabsf(v.x) >= thr) | (fabsf(v.y) >= thr)
                             | (fabsf(v.z) >= thr) | (fabsf(v.w) >= thr);
                    if (any) {                       // ~18% of float4s
                        float vv[4] = {v.x, v.y, v.z, v.w};
                        #pragma unroll
                        for (int c = 0; c < 4; c++) {
                            float f = vv[c];
                            if (fabsf(f) >= thr) {
                                if (f < 0.0f) {
                                    if (nl < STASH) pL[nl++] = f;
                                    else { unsigned o = atomicAdd(&s_u[1], 1u); if (o < OVF) ovfL[o] = f; }
                                } else {
                                    if (nh < STASH) pH[nh++] = f;
                                    else { unsigned o = atomicAdd(&s_u[2], 1u); if (o < OVF) ovfH[o] = f; }
                                }
                            }
                        }
                    }
                }
            }
        } else {
            // general fallback: two-compare path
            float w1 = g_win[slice][0];
            float w2 = g_win[slice][1];
            #pragma unroll 4
            for (int k = 0; k < GCHUNK / 4 / 256; k++) {
                float4 v = xs[tid + k * 256];
                float vv[4] = {v.x, v.y, v.z, v.w};
                #pragma unroll
                for (int c = 0; c < 4; c++) {
                    float f = vv[c];
                    if (f < w1) {
                        if (nl < STASH) pL[nl++] = f;
                        else { unsigned o = atomicAdd(&s_u[1], 1u); if (o < OVF) ovfL[o] = f; }
                    }
                    if (f >= w2) {
                        if (nh < STASH) pH[nh++] = f;
                        else { unsigned o = atomicAdd(&s_u[2], 1u); if (o < OVF) ovfH[o] = f; }
                    }
                }
            }
        }

        // block exclusive scan of stash counts
        unsigned cumL = nl, cumH = nh;
        #pragma unroll
        for (int o = 1; o < 32; o <<= 1) {
            unsigned tL = __shfl_up_sync(0xffffffffu, cumL, o);
            unsigned tH = __shfl_up_sync(0xffffffffu, cumH, o);
            if (lane >= o) { cumL += tL; cumH += tH; }
        }
        if (lane == 31) { wsumL[wrp] = cumL; wsumH[wrp] = cumH; }
        __syncthreads();

        if (tid == 0) {
            unsigned aL = 0, aH = 0;
            #pragma unroll
            for (int w = 0; w < 8; w++) {
                unsigned tL = wsumL[w], tH = wsumH[w];
                wsumL[w] = aL; wsumH[w] = aH;
                aL += tL; aH += tH;
            }
            unsigned ovl = s_u[1] < OVF ? s_u[1] : OVF;
            unsigned ovh = s_u[2] < OVF ? s_u[2] : OVF;
            s_u[1] = ovl; s_u[2] = ovh;
            s_u[7] = aL; s_u[8] = aH;
            s_u[5] = atomicAdd(&g_ncand[slice][0], aL + ovl);
            s_u[6] = atomicAdd(&g_ncand[slice][1], aH + ovh);
        }
        __syncthreads();

        unsigned offL = s_u[5] + wsumL[wrp] + cumL - nl;
        unsigned offH = s_u[6] + wsumH[wrp] + cumH - nh;
        for (unsigned j = 0; j < nl; j++) {
            unsigned gi = offL + j;
            if (gi < CAND_MAX) g_cand[slice][0][gi] = pL[j];
        }
        for (unsigned j = 0; j < nh; j++) {
            unsigned gi = offH + j;
            if (gi < CAND_MAX) g_cand[slice][1][gi] = pH[j];
        }
        for (unsigned j = tid; j < s_u[1]; j += 256) {
            unsigned gi = s_u[5] + s_u[7] + j;
            if (gi < CAND_MAX) g_cand[slice][0][gi] = ovfL[j];
        }
        for (unsigned j = tid; j < s_u[2]; j += 256) {
            unsigned gi = s_u[6] + s_u[8] + j;
            if (gi < CAND_MAX) g_cand[slice][1][gi] = ovfH[j];
        }

        // publish + last-block select
        __threadfence();
        __syncthreads();
        if (tid == 0) s_u[9] = atomicAdd(&g_done[slice], 1u);
        __syncthreads();
        if (s_u[9] == GBLK - 1) {
            __threadfence();   // acquire all gather blocks' writes
            unsigned* hist  = (unsigned*)stL;
            unsigned* tsum  = (unsigned*)stH;
            unsigned* red_u = (unsigned*)stH + 256;
            do_select(slice, 0, hist, tsum, red_u, &s_u[10]);
            __syncthreads();
            do_select(slice, 1, hist, tsum, red_u, &s_u[10]);
            __threadfence();
            __syncthreads();
            if (tid == 0) atomicExch(&g_flag[slice], 1u);
        }
    } else {
        // ---------------- normalize role ----------------
        if (tid == 0) {
            unsigned ns = 64;
            while (poll_u32(&g_flag[slice]) == 0u) {
                __nanosleep(ns);
                if (ns < 2048) ns <<= 1;
            }
            __threadfence();
            s_q[0] = __ldcg(&g_q[slice][0]);
            s_q[1] = __ldcg(&g_q[slice][1]);
        }
        __syncthreads();
        float vmin = s_q[0], vmax = s_q[1];
        float a = 1.0f / (vmax - vmin + 1e-8f);
        float b = -vmin * a;

        size_t base = (size_t)slice * N_PER + (size_t)part * NCHUNK;
        const float4* xi = (const float4*)(x + base);
        float4* xo = (float4*)(out + base);
        const int NV = NCHUNK / 4;       // 2048
        #pragma unroll 4
        for (int i = tid; i < NV; i += 256) {
            float4 v = __ldcs(&xi[i]);       // L2-hot; evict after use
            v.x = __saturatef(fmaf(v.x, a, b));
            v.y = __saturatef(fmaf(v.y, a, b));
            v.z = __saturatef(fmaf(v.z, a, b));
            v.w = __saturatef(fmaf(v.w, a, b));
            __stcs(&xo[i], v);               // streaming store
        }
    }
}

extern "C" void kernel_launch(void* const* d_in, const int* in_sizes, int n_in,
                              void* d_out, int out_size) {
    const float* x = (const float*)d_in[0];
    float* out = (float*)d_out;
    int slices = out_size / N_PER;
    if (slices > MAX_SLICES) slices = MAX_SLICES;
    if (slices < 1) return;

    sample_kernel<<<slices, 256>>>(x);
    mega_kernel<<<slices * TPS, 256>>>(x, out);
}

// round 13
// speedup vs baseline: 1.2606x; 1.2606x over previous
#include <cuda_runtime.h>
#include <stdint.h>

// Problem geometry (x: (32, 7, 512, 512) fp32; per-(B,C) slice quantile over H*W)
#define MAX_SLICES 224
#define N_PER      262144           // 512*512
#define M_SAMP     4096
#define NGROUP     512              // sample groups of 8 contiguous floats
#define CAND_MAX   32768

// Sample-rank brackets among 4096 sorted samples.
#define R_LO 100
#define R_HI 3995

#define NBIN 4096                   // top-12 bits of monotone key

#define GBLK   32                   // gather chunks per slice
#define GCHUNK (N_PER / GBLK)       // 8192 elements
#define NBLKN  32                   // normalize chunks per slice
#define NCHUNK (N_PER / NBLKN)      // 8192 elements
#define STASH  10                   // per-thread stash (mean ~1.6 of 32 elems)
#define SROW   (STASH + 1)          // padded row, conflict-free
#define OVF    512                  // per-block overflow fallback

// ---- static device scratch (no allocations allowed) ----
__device__ float    g_win[MAX_SLICES][2];    // w1 (lo edge), w2 (hi edge)
__device__ float    g_thr[MAX_SLICES];       // symmetric threshold t (or -1)
__device__ unsigned g_ncand[MAX_SLICES][2];
__device__ float    g_cand[MAX_SLICES][2][CAND_MAX];
__device__ float    g_q[MAX_SLICES][2];
__device__ unsigned g_done[MAX_SLICES];

// Monotone float <-> uint key
__device__ __forceinline__ unsigned fkey(float f) {
    unsigned u = __float_as_uint(f);
    return (u & 0x80000000u) ? ~u : (u | 0x80000000u);
}
__device__ __forceinline__ float funkey(unsigned k) {
    return (k & 0x80000000u) ? __uint_as_float(k & 0x7FFFFFFFu)
                             : __uint_as_float(~k);
}

// ============================================================
// Kernel 1: per-slice sample histogram -> tail thresholds
// ============================================================
__global__ void sample_kernel(const float* __restrict__ x) {
    __shared__ unsigned hist[NBIN];
    __shared__ unsigned toff[257];
    __shared__ unsigned sh_bin[2];
    __shared__ unsigned wsum[8];

    int slice = blockIdx.x;
    int tid = threadIdx.x;
    const float* xs = x + (size_t)slice * N_PER;

    for (int i = tid; i < NBIN; i += 256) hist[i] = 0;
    __syncthreads();

    #pragma unroll
    for (int g = tid; g < NGROUP; g += 256) {
        const float4* gp = (const float4*)(xs + (size_t)g * (N_PER / NGROUP));
        #pragma unroll
        for (int j = 0; j < 2; j++) {
            float4 v = gp[j];
            atomicAdd(&hist[fkey(v.x) >> 20], 1u);
            atomicAdd(&hist[fkey(v.y) >> 20], 1u);
            atomicAdd(&hist[fkey(v.z) >> 20], 1u);
            atomicAdd(&hist[fkey(v.w) >> 20], 1u);
        }
    }
    __syncthreads();

    unsigned s = 0;
    #pragma unroll
    for (int b = 0; b < 16; b++) s += hist[tid * 16 + b];

    int lane = tid & 31, wrp = tid >> 5;
    unsigned cum = s;
    #pragma unroll
    for (int o = 1; o < 32; o <<= 1) {
        unsigned t = __shfl_up_sync(0xffffffffu, cum, o);
        if (lane >= o) cum += t;
    }
    if (lane == 31) wsum[wrp] = cum;
    __syncthreads();
    if (tid == 0) {
        unsigned acc = 0;
        #pragma unroll
        for (int w = 0; w < 8; w++) { unsigned t = wsum[w]; wsum[w] = acc; acc += t; }
    }
    __syncthreads();
    toff[tid] = wsum[wrp] + cum - s;
    if (tid == 255) toff[256] = M_SAMP;
    __syncthreads();

    const int ranks[2] = {R_LO, R_HI};
    if (tid < 2) {
        unsigned R = (unsigned)ranks[tid];
        int lo = 0, hi = 256;
        while (hi - lo > 1) {
            int mid = (lo + hi) >> 1;
            if (toff[mid] <= R) lo = mid; else hi = mid;
        }
        unsigned acc = toff[lo];
        int bin = lo * 16;
        #pragma unroll
        for (int b = 0; b < 16; b++) {
            unsigned h = hist[lo * 16 + b];
            if (acc + h > R) { bin = lo * 16 + b; break; }
            acc += h;
        }
        sh_bin[tid] = (unsigned)bin;
    }
    __syncthreads();

    if (tid == 0) {
        float w1 = funkey((sh_bin[0] + 1u) << 20);   // upper edge of lo-tail bin
        float w2 = funkey(sh_bin[1] << 20);          // lower edge of hi-tail bin
        g_win[slice][0] = w1;
        g_win[slice][1] = w2;
        g_thr[slice] = (w1 < 0.0f && w2 > 0.0f) ? fminf(-w1, w2) : -1.0f;
        g_ncand[slice][0] = 0; g_ncand[slice][1] = 0;
        g_done[slice] = 0;
    }
}

// ============================================================
// Inline select: exact radix-select among candidates of (slice, w).
// w=0: stash contains ALL f below its threshold  -> base count 0.
// w=1: stash contains ALL f >= its threshold     -> base = N - n.
// ============================================================
__device__ void do_select(int slice, int w, unsigned* hist, unsigned* tsum,
                          unsigned* red_u, volatile unsigned* sh2) {
    int tid = threadIdx.x;
    unsigned n_raw = g_ncand[slice][w];
    unsigned n = n_raw > CAND_MAX ? CAND_MAX : n_raw;
    unsigned cnt = (w == 0) ? 0u : (unsigned)N_PER - n_raw;

    double pos  = (w == 0) ? 0.01 * (double)(N_PER - 1) : 0.99 * (double)(N_PER - 1);
    long long K = (long long)pos;
    double frac = pos - (double)K;

    if (n < 2) {
        if (tid == 0) g_q[slice][w] = (n == 1) ? g_cand[slice][w][0] : 0.0f;
        return;
    }
    long long rl = K - (long long)cnt;
    if (rl < 0) rl = 0;
    if (rl > (long long)n - 2) rl = (long long)n - 2;
    int r = (int)rl;
    const float* cand = g_cand[slice][w];

    unsigned prefix = 0, pmask = 0;
    int rrem = r;
    const int shifts[3] = {21, 10, 0};
    const int bitsv[3]  = {11, 11, 10};
    #pragma unroll
    for (int p = 0; p < 3; p++) {
        int shift = shifts[p];
        unsigned nb = 1u << bitsv[p];
        unsigned dmask = nb - 1u;
        unsigned per = nb / 256;
        for (unsigned i = tid; i < 2048; i += 256) hist[i] = 0;
        __syncthreads();
        for (unsigned i = tid; i < n; i += 256) {
            unsigned u = fkey(cand[i]);
            if ((u & pmask) == prefix)
                atomicAdd(&hist[(u >> shift) & dmask], 1u);
        }
        __syncthreads();
        unsigned s = 0;
        for (unsigned q2 = 0; q2 < per; q2++) s += hist[tid * per + q2];
        tsum[tid] = s;
        __syncthreads();

        if (tid < 32) {
            unsigned part[8];
            unsigned ls = 0;
            #pragma unroll
            for (int j = 0; j < 8; j++) { part[j] = tsum[tid * 8 + j]; ls += part[j]; }
            unsigned cum = ls;
            #pragma unroll
            for (int o = 1; o < 32; o <<= 1) {
                unsigned t = __shfl_up_sync(0xffffffffu, cum, o);
                if (tid >= o) cum += t;
            }
            unsigned excl = cum - ls;
            unsigned ball = __ballot_sync(0xffffffffu, cum > (unsigned)rrem);
            int cross = __ffs(ball) - 1;
            if (tid == cross) {
                unsigned acc = excl;
                int tc = tid * 8;
                #pragma unroll
                for (int j = 0; j < 8; j++) {
                    if (acc + part[j] > (unsigned)rrem) { tc = tid * 8 + j; break; }
                    acc += part[j];
                }
                unsigned d = (unsigned)tc * per;
                for (unsigned b = 0; b < per; b++) {
                    unsigned h = hist[tc * per + b];
                    if (acc + h > (unsigned)rrem) { d = (unsigned)tc * per + b; break; }
                    acc += h;
                }
                sh2[0] = d;
                sh2[1] = (unsigned)rrem - acc;
            }
        }
        __syncthreads();
        prefix |= sh2[0] << shift;
        pmask  |= dmask << shift;
        rrem = (int)sh2[1];
        __syncthreads();
    }
    unsigned v0key = prefix;

    unsigned cle = 0, mgt = 0xFFFFFFFFu;
    for (unsigned i = tid; i < n; i += 256) {
        unsigned u = fkey(cand[i]);
        cle += (u <= v0key);
        if (u > v0key && u < mgt) mgt = u;
    }
    red_u[tid] = cle; __syncthreads();
    for (int o = 128; o; o >>= 1) {
        if (tid < o) red_u[tid] += red_u[tid + o];
        __syncthreads();
    }
    unsigned cle_tot = red_u[0]; __syncthreads();
    red_u[tid] = mgt; __syncthreads();
    for (int o = 128; o; o >>= 1) {
        if (tid < o) red_u[tid] = (red_u[tid + o] < red_u[tid]) ? red_u[tid + o] : red_u[tid];
        __syncthreads();
    }
    unsigned mgt_tot = red_u[0];
    __syncthreads();

    if (tid == 0) {
        unsigned v1key = (cle_tot >= (unsigned)(r + 2)) ? v0key
                       : ((mgt_tot != 0xFFFFFFFFu) ? mgt_tot : v0key);
        double v0 = (double)funkey(v0key);
        double v1 = (double)funkey(v1key);
        g_q[slice][w] = (float)(v0 + frac * (v1 - v0));
    }
}

// ============================================================
// Kernel 2: gather (fast |f|>=t path) + last-block inline select.
// No cross-phase waits: select runs in the slice's last gather block.
// ============================================================
__global__ void __launch_bounds__(256) gather_kernel(const float* __restrict__ x) {
    __shared__ float stL[256 * SROW];        // 11.3 KB
    __shared__ float stH[256 * SROW];        // 11.3 KB (aliased in select)
    __shared__ float ovfL[OVF], ovfH[OVF];   // 4 KB
    __shared__ unsigned s_u[16];
    __shared__ unsigned wsumL[8], wsumH[8];

    int tid = threadIdx.x;
    int lane = tid & 31, wrp = tid >> 5;
    int slice = blockIdx.x / GBLK;
    int part  = blockIdx.x % GBLK;

    if (tid == 0) { s_u[1] = 0; s_u[2] = 0; }
    __syncthreads();

    const float4* xs = (const float4*)(x + (size_t)slice * N_PER
                                         + (size_t)part * GCHUNK);
    float thr = g_thr[slice];

    float* pL = &stL[tid * SROW];
    float* pH = &stH[tid * SROW];
    unsigned nl = 0, nh = 0;

    if (thr >= 0.0f) {
        // symmetric fast path: 4x FSETP(|f|,t) OR-folded, one branch/float4
        #pragma unroll
        for (int kb = 0; kb < 2; kb++) {
            float4 r[4];
            #pragma unroll
            for (int k = 0; k < 4; k++)
                r[k] = xs[tid + (kb * 4 + k) * 256];
            #pragma unroll
            for (int k = 0; k < 4; k++) {
                float4 v = r[k];
                bool any = (fabsf(v.x) >= thr) | (fabsf(v.y) >= thr)
                         | (fabsf(v.z) >= thr) | (fabsf(v.w) >= thr);
                if (any) {                       // ~18% of float4s
                    float vv[4] = {v.x, v.y, v.z, v.w};
                    #pragma unroll
                    for (int c = 0; c < 4; c++) {
                        float f = vv[c];
                        if (fabsf(f) >= thr) {
                            if (f < 0.0f) {
                                if (nl < STASH) pL[nl++] = f;
                                else { unsigned o = atomicAdd(&s_u[1], 1u); if (o < OVF) ovfL[o] = f; }
                            } else {
                                if (nh < STASH) pH[nh++] = f;
                                else { unsigned o = atomicAdd(&s_u[2], 1u); if (o < OVF) ovfH[o] = f; }
                            }
                        }
                    }
                }
            }
        }
    } else {
        // general fallback: two-compare path
        float w1 = g_win[slice][0];
        float w2 = g_win[slice][1];
        #pragma unroll 4
        for (int k = 0; k < GCHUNK / 4 / 256; k++) {
            float4 v = xs[tid + k * 256];
            float vv[4] = {v.x, v.y, v.z, v.w};
            #pragma unroll
            for (int c = 0; c < 4; c++) {
                float f = vv[c];
                if (f < w1) {
                    if (nl < STASH) pL[nl++] = f;
                    else { unsigned o = atomicAdd(&s_u[1], 1u); if (o < OVF) ovfL[o] = f; }
                }
                if (f >= w2) {
                    if (nh < STASH) pH[nh++] = f;
                    else { unsigned o = atomicAdd(&s_u[2], 1u); if (o < OVF) ovfH[o] = f; }
                }
            }
        }
    }

    // block exclusive scan of stash counts
    unsigned cumL = nl, cumH = nh;
    #pragma unroll
    for (int o = 1; o < 32; o <<= 1) {
        unsigned tL = __shfl_up_sync(0xffffffffu, cumL, o);
        unsigned tH = __shfl_up_sync(0xffffffffu, cumH, o);
        if (lane >= o) { cumL += tL; cumH += tH; }
    }
    if (lane == 31) { wsumL[wrp] = cumL; wsumH[wrp] = cumH; }
    __syncthreads();

    if (tid == 0) {
        unsigned aL = 0, aH = 0;
        #pragma unroll
        for (int w = 0; w < 8; w++) {
            unsigned tL = wsumL[w], tH = wsumH[w];
            wsumL[w] = aL; wsumH[w] = aH;
            aL += tL; aH += tH;
        }
        unsigned ovl = s_u[1] < OVF ? s_u[1] : OVF;
        unsigned ovh = s_u[2] < OVF ? s_u[2] : OVF;
        s_u[1] = ovl; s_u[2] = ovh;
        s_u[7] = aL; s_u[8] = aH;
        s_u[5] = atomicAdd(&g_ncand[slice][0], aL + ovl);
        s_u[6] = atomicAdd(&g_ncand[slice][1], aH + ovh);
    }
    __syncthreads();

    unsigned offL = s_u[5] + wsumL[wrp] + cumL - nl;
    unsigned offH = s_u[6] + wsumH[wrp] + cumH - nh;
    for (unsigned j = 0; j < nl; j++) {
        unsigned gi = offL + j;
        if (gi < CAND_MAX) g_cand[slice][0][gi] = pL[j];
    }
    for (unsigned j = 0; j < nh; j++) {
        unsigned gi = offH + j;
        if (gi < CAND_MAX) g_cand[slice][1][gi] = pH[j];
    }
    for (unsigned j = tid; j < s_u[1]; j += 256) {
        unsigned gi = s_u[5] + s_u[7] + j;
        if (gi < CAND_MAX) g_cand[slice][0][gi] = ovfL[j];
    }
    for (unsigned j = tid; j < s_u[2]; j += 256) {
        unsigned gi = s_u[6] + s_u[8] + j;
        if (gi < CAND_MAX) g_cand[slice][1][gi] = ovfH[j];
    }

    // publish + last-block select
    __threadfence();
    __syncthreads();
    if (tid == 0) s_u[9] = atomicAdd(&g_done[slice], 1u);
    __syncthreads();
    if (s_u[9] == GBLK - 1) {
        __threadfence();   // acquire all gather blocks' writes
        unsigned* hist  = (unsigned*)stL;
        unsigned* tsum  = (unsigned*)stH;
        unsigned* red_u = (unsigned*)stH + 256;
        do_select(slice, 0, hist, tsum, red_u, &s_u[10]);
        __syncthreads();
        do_select(slice, 1, hist, tsum, red_u, &s_u[10]);
    }
}

// ============================================================
// Kernel 3: normalize + clamp. Slices walked in REVERSE order:
// the last-gathered slices are still L2-resident when this kernel
// starts, so its first reads hit L2 instead of DRAM.
// ============================================================
__global__ void __launch_bounds__(256) normalize_kernel(const float* __restrict__ x,
                                                        float* __restrict__ out) {
    int slices = gridDim.x / NBLKN;
    int slice = slices - 1 - (int)(blockIdx.x / NBLKN);   // reverse order
    int part  = (int)(blockIdx.x % NBLKN);

    float vmin = g_q[slice][0];
    float vmax = g_q[slice][1];
    float a = 1.0f / (vmax - vmin + 1e-8f);
    float b = -vmin * a;

    size_t base = (size_t)slice * N_PER + (size_t)part * NCHUNK;
    const float4* xi = (const float4*)(x + base);
    float4* xo = (float4*)(out + base);
    const int NV = NCHUNK / 4;       // 2048
    int tid = threadIdx.x;
    #pragma unroll 4
    for (int i = tid; i < NV; i += 256) {
        float4 v = __ldcs(&xi[i]);       // evict after use
        v.x = __saturatef(fmaf(v.x, a, b));
        v.y = __saturatef(fmaf(v.y, a, b));
        v.z = __saturatef(fmaf(v.z, a, b));
        v.w = __saturatef(fmaf(v.w, a, b));
        __stcs(&xo[i], v);               // streaming store
    }
}

extern "C" void kernel_launch(void* const* d_in, const int* in_sizes, int n_in,
                              void* d_out, int out_size) {
    const float* x = (const float*)d_in[0];
    float* out = (float*)d_out;
    int slices = out_size / N_PER;
    if (slices > MAX_SLICES) slices = MAX_SLICES;
    if (slices < 1) return;

    sample_kernel<<<slices, 256>>>(x);
    gather_kernel<<<slices * GBLK, 256>>>(x);
    normalize_kernel<<<slices * NBLKN, 256>>>(x, out);
}

// round 14
// speedup vs baseline: 1.4438x; 1.1454x over previous
#include <cuda_runtime.h>
#include <stdint.h>

// Problem geometry (x: (32, 7, 512, 512) fp32; per-(B,C) slice quantile over H*W)
#define MAX_SLICES 224
#define N_PER      262144           // 512*512
#define M_SAMP     4096
#define NGROUP     512              // sample groups of 8 contiguous floats
#define CAND_MAX   32768

// Sample-rank brackets among 4096 sorted samples.
#define R_LO 100
#define R_HI 3995

#define NBIN 4096                   // top-12 bits of monotone key

// work partition (two-phase tickets, forward order — R11 skeleton)
#define GBLK   32                   // gather chunks per slice
#define GCHUNK (N_PER / GBLK)       // 8192 elements
#define NBLKN  32                   // normalize chunks per slice
#define NCHUNK (N_PER / NBLKN)      // 8192 elements
#define TPS    (GBLK + NBLKN)
#define STASH  10                   // per-thread stash (mean ~0.7-1.6 of 32 elems)
#define SROW   (STASH + 1)          // padded row, conflict-free
#define OVF    512                  // per-block overflow fallback

// minimum sample-tail count beyond +-2.0 to certify the bit30 fast path:
// 75/4096 minus 4 sigma still implies true tail mass > 1.07% > 2623/262144.
#define TAIL_MIN 75

// ---- static device scratch (no allocations allowed) ----
__device__ float    g_win[MAX_SLICES][2];    // w1 (lo edge), w2 (hi edge)
__device__ float    g_thr[MAX_SLICES];       // symmetric threshold t (or -1)
__device__ int      g_mode[MAX_SLICES];      // 1 = bit30 (+-2.0) certified path
__device__ unsigned g_ncand[MAX_SLICES][2];
__device__ float    g_cand[MAX_SLICES][2][CAND_MAX];
__device__ float    g_q[MAX_SLICES][2];
__device__ unsigned g_ticket;
__device__ unsigned g_done[MAX_SLICES];
__device__ unsigned g_flag[MAX_SLICES];

// Monotone float <-> uint key
__device__ __forceinline__ unsigned fkey(float f) {
    unsigned u = __float_as_uint(f);
    return (u & 0x80000000u) ? ~u : (u | 0x80000000u);
}
__device__ __forceinline__ float funkey(unsigned k) {
    return (k & 0x80000000u) ? __uint_as_float(k & 0x7FFFFFFFu)
                             : __uint_as_float(~k);
}
__device__ __forceinline__ unsigned poll_u32(const unsigned* p) {
    unsigned v;
    asm volatile("ld.global.cg.u32 %0, [%1];" : "=r"(v) : "l"(p) : "memory");
    return v;
}

// ============================================================
// Kernel 1: per-slice sample histogram -> tail thresholds
// + certification of the bit30 (|f|>=2.0) fast path
// ============================================================
__global__ void sample_kernel(const float* __restrict__ x) {
    __shared__ unsigned hist[NBIN];
    __shared__ unsigned toff[257];
    __shared__ unsigned sh_bin[2];
    __shared__ unsigned wsum[8];
    __shared__ unsigned s_lo, s_hi;

    int slice = blockIdx.x;
    int tid = threadIdx.x;
    const float* xs = x + (size_t)slice * N_PER;

    if (slice == 0 && tid == 0) g_ticket = 0;
    if (tid == 0) { s_lo = 0; s_hi = 0; }

    for (int i = tid; i < NBIN; i += 256) hist[i] = 0;
    __syncthreads();

    unsigned clo = 0, chi = 0;
    #pragma unroll
    for (int g = tid; g < NGROUP; g += 256) {
        const float4* gp = (const float4*)(xs + (size_t)g * (N_PER / NGROUP));
        #pragma unroll
        for (int j = 0; j < 2; j++) {
            float4 v = gp[j];
            float vv[4] = {v.x, v.y, v.z, v.w};
            #pragma unroll
            for (int c = 0; c < 4; c++) {
                atomicAdd(&hist[fkey(vv[c]) >> 20], 1u);
                clo += (vv[c] <= -2.0f);
                chi += (vv[c] >=  2.0f);
            }
        }
    }
    int lane = tid & 31, wrp = tid >> 5;
    #pragma unroll
    for (int o = 16; o; o >>= 1) {
        clo += __shfl_down_sync(0xffffffffu, clo, o);
        chi += __shfl_down_sync(0xffffffffu, chi, o);
    }
    if (lane == 0) { atomicAdd(&s_lo, clo); atomicAdd(&s_hi, chi); }
    __syncthreads();

    unsigned s = 0;
    #pragma unroll
    for (int b = 0; b < 16; b++) s += hist[tid * 16 + b];

    unsigned cum = s;
    #pragma unroll
    for (int o = 1; o < 32; o <<= 1) {
        unsigned t = __shfl_up_sync(0xffffffffu, cum, o);
        if (lane >= o) cum += t;
    }
    if (lane == 31) wsum[wrp] = cum;
    __syncthreads();
    if (tid == 0) {
        unsigned acc = 0;
        #pragma unroll
        for (int w = 0; w < 8; w++) { unsigned t = wsum[w]; wsum[w] = acc; acc += t; }
    }
    __syncthreads();
    toff[tid] = wsum[wrp] + cum - s;
    if (tid == 255) toff[256] = M_SAMP;
    __syncthreads();

    const int ranks[2] = {R_LO, R_HI};
    if (tid < 2) {
        unsigned R = (unsigned)ranks[tid];
        int lo = 0, hi = 256;
        while (hi - lo > 1) {
            int mid = (lo + hi) >> 1;
            if (toff[mid] <= R) lo = mid; else hi = mid;
        }
        unsigned acc = toff[lo];
        int bin = lo * 16;
        #pragma unroll
        for (int b = 0; b < 16; b++) {
            unsigned h = hist[lo * 16 + b];
            if (acc + h > R) { bin = lo * 16 + b; break; }
            acc += h;
        }
        sh_bin[tid] = (unsigned)bin;
    }
    __syncthreads();

    if (tid == 0) {
        float w1 = funkey((sh_bin[0] + 1u) << 20);   // upper edge of lo-tail bin
        float w2 = funkey(sh_bin[1] << 20);          // lower edge of hi-tail bin
        g_win[slice][0] = w1;
        g_win[slice][1] = w2;
        g_thr[slice] = (w1 < 0.0f && w2 > 0.0f) ? fminf(-w1, w2) : -1.0f;
        g_mode[slice] = (s_lo >= TAIL_MIN && s_hi >= TAIL_MIN) ? 1 : 0;
        g_ncand[slice][0] = 0; g_ncand[slice][1] = 0;
        g_done[slice] = 0;
        g_flag[slice] = 0;
    }
}

// ============================================================
// Inline select: exact radix-select among candidates of (slice, w).
// w=0: stash contains ALL f below its threshold  -> base count 0.
// w=1: stash contains ALL f >= its threshold     -> base = N - n.
// ============================================================
__device__ void do_select(int slice, int w, unsigned* hist, unsigned* tsum,
                          unsigned* red_u, volatile unsigned* sh2) {
    int tid = threadIdx.x;
    unsigned n_raw = g_ncand[slice][w];
    unsigned n = n_raw > CAND_MAX ? CAND_MAX : n_raw;
    unsigned cnt = (w == 0) ? 0u : (unsigned)N_PER - n_raw;

    double pos  = (w == 0) ? 0.01 * (double)(N_PER - 1) : 0.99 * (double)(N_PER - 1);
    long long K = (long long)pos;
    double frac = pos - (double)K;

    if (n < 2) {
        if (tid == 0) g_q[slice][w] = (n == 1) ? g_cand[slice][w][0] : 0.0f;
        return;
    }
    long long rl = K - (long long)cnt;
    if (rl < 0) rl = 0;
    if (rl > (long long)n - 2) rl = (long long)n - 2;
    int r = (int)rl;
    const float* cand = g_cand[slice][w];

    unsigned prefix = 0, pmask = 0;
    int rrem = r;
    const int shifts[3] = {21, 10, 0};
    const int bitsv[3]  = {11, 11, 10};
    #pragma unroll
    for (int p = 0; p < 3; p++) {
        int shift = shifts[p];
        unsigned nb = 1u << bitsv[p];
        unsigned dmask = nb - 1u;
        unsigned per = nb / 256;
        for (unsigned i = tid; i < 2048; i += 256) hist[i] = 0;
        __syncthreads();
        for (unsigned i = tid; i < n; i += 256) {
            unsigned u = fkey(cand[i]);
            if ((u & pmask) == prefix)
                atomicAdd(&hist[(u >> shift) & dmask], 1u);
        }
        __syncthreads();
        unsigned s = 0;
        for (unsigned q2 = 0; q2 < per; q2++) s += hist[tid * per + q2];
        tsum[tid] = s;
        __syncthreads();

        if (tid < 32) {
            unsigned part[8];
            unsigned ls = 0;
            #pragma unroll
            for (int j = 0; j < 8; j++) { part[j] = tsum[tid * 8 + j]; ls += part[j]; }
            unsigned cum = ls;
            #pragma unroll
            for (int o = 1; o < 32; o <<= 1) {
                unsigned t = __shfl_up_sync(0xffffffffu, cum, o);
                if (tid >= o) cum += t;
            }
            unsigned excl = cum - ls;
            unsigned ball = __ballot_sync(0xffffffffu, cum > (unsigned)rrem);
            int cross = __ffs(ball) - 1;
            if (tid == cross) {
                unsigned acc = excl;
                int tc = tid * 8;
                #pragma unroll
                for (int j = 0; j < 8; j++) {
                    if (acc + part[j] > (unsigned)rrem) { tc = tid * 8 + j; break; }
                    acc += part[j];
                }
                unsigned d = (unsigned)tc * per;
                for (unsigned b = 0; b < per; b++) {
                    unsigned h = hist[tc * per + b];
                    if (acc + h > (unsigned)rrem) { d = (unsigned)tc * per + b; break; }
                    acc += h;
                }
                sh2[0] = d;
                sh2[1] = (unsigned)rrem - acc;
            }
        }
        __syncthreads();
        prefix |= sh2[0] << shift;
        pmask  |= dmask << shift;
        rrem = (int)sh2[1];
        __syncthreads();
    }
    unsigned v0key = prefix;

    unsigned cle = 0, mgt = 0xFFFFFFFFu;
    for (unsigned i = tid; i < n; i += 256) {
        unsigned u = fkey(cand[i]);
        cle += (u <= v0key);
        if (u > v0key && u < mgt) mgt = u;
    }
    red_u[tid] = cle; __syncthreads();
    for (int o = 128; o; o >>= 1) {
        if (tid < o) red_u[tid] += red_u[tid + o];
        __syncthreads();
    }
    unsigned cle_tot = red_u[0]; __syncthreads();
    red_u[tid] = mgt; __syncthreads();
    for (int o = 128; o; o >>= 1) {
        if (tid < o) red_u[tid] = (red_u[tid + o] < red_u[tid]) ? red_u[tid + o] : red_u[tid];
        __syncthreads();
    }
    unsigned mgt_tot = red_u[0];
    __syncthreads();

    if (tid == 0) {
        unsigned v1key = (cle_tot >= (unsigned)(r + 2)) ? v0key
                       : ((mgt_tot != 0xFFFFFFFFu) ? mgt_tot : v0key);
        double v0 = (double)funkey(v0key);
        double v1 = (double)funkey(v1key);
        g_q[slice][w] = (float)(v0 + frac * (v1 - v0));
    }
}

// ============================================================
// Mega kernel (R11 skeleton): gather tickets first (slice-
// ascending), then normalize tickets (forward order).
// Gather hot path, certified slices: bit30 test —
// |f| >= 2.0 <=> (word & 0x40000000) != 0; OR-fold 4 words.
// ============================================================
__global__ void __launch_bounds__(256) mega_kernel(const float* __restrict__ x,
                                                   float* __restrict__ out) {
    __shared__ float stL[256 * SROW];        // 11.3 KB
    __shared__ float stH[256 * SROW];        // 11.3 KB (aliased in select)
    __shared__ float ovfL[OVF], ovfH[OVF];   // 4 KB
    __shared__ unsigned s_u[16];
    __shared__ unsigned wsumL[8], wsumH[8];
    __shared__ float s_q[2];

    int tid = threadIdx.x;
    int lane = tid & 31, wrp = tid >> 5;
    int slices = gridDim.x / TPS;
    unsigned gather_total = (unsigned)(GBLK * slices);

    if (tid == 0) {
        s_u[0] = atomicAdd(&g_ticket, 1u);
        s_u[1] = 0; s_u[2] = 0;
    }
    __syncthreads();
    unsigned ticket = s_u[0];

    if (ticket < gather_total) {
        // ---------------- gather role ----------------
        int slice = (int)(ticket / GBLK);
        int part  = (int)(ticket % GBLK);
        const float4* xs = (const float4*)(x + (size_t)slice * N_PER
                                             + (size_t)part * GCHUNK);

        float* pL = &stL[tid * SROW];
        float* pH = &stH[tid * SROW];
        unsigned nl = 0, nh = 0;
        int mode = g_mode[slice];

        if (mode == 1) {
            // certified bit30 path: |f| >= 2.0 <=> bit30 set
            #pragma unroll
            for (int kb = 0; kb < 2; kb++) {
                float4 r[4];
                #pragma unroll
                for (int k = 0; k < 4; k++)
                    r[k] = xs[tid + (kb * 4 + k) * 256];
                #pragma unroll
                for (int k = 0; k < 4; k++) {
                    float4 v = r[k];
                    unsigned u0 = __float_as_uint(v.x), u1 = __float_as_uint(v.y);
                    unsigned u2 = __float_as_uint(v.z), u3 = __float_as_uint(v.w);
                    if (((u0 | u1) | (u2 | u3)) & 0x40000000u) {   // ~17% of float4s
                        float vv[4] = {v.x, v.y, v.z, v.w};
                        #pragma unroll
                        for (int c = 0; c < 4; c++) {
                            float f = vv[c];
                            if (__float_as_uint(f) & 0x40000000u) {
                                if (f < 0.0f) {
                                    if (nl < STASH) pL[nl++] = f;
                                    else { unsigned o = atomicAdd(&s_u[1], 1u); if (o < OVF) ovfL[o] = f; }
                                } else {
                                    if (nh < STASH) pH[nh++] = f;
                                    else { unsigned o = atomicAdd(&s_u[2], 1u); if (o < OVF) ovfH[o] = f; }
                                }
                            }
                        }
                    }
                }
            }
        } else {
            float thr = g_thr[slice];
            if (thr >= 0.0f) {
                // symmetric FSETP path
                #pragma unroll
                for (int kb = 0; kb < 2; kb++) {
                    float4 r[4];
                    #pragma unroll
                    for (int k = 0; k < 4; k++)
                        r[k] = xs[tid + (kb * 4 + k) * 256];
                    #pragma unroll
                    for (int k = 0; k < 4; k++) {
                        float4 v = r[k];
                        bool any = (fabsf(v.x) >= thr) | (fabsf(v.y) >= thr)
                                 | (fabsf(v.z) >= thr) | (fabsf(v.w) >= thr);
                        if (any) {
                            float vv[4] = {v.x, v.y, v.z, v.w};
                            #pragma unroll
                            for (int c = 0; c < 4; c++) {
                                float f = vv[c];
                                if (fabsf(f) >= thr) {
                                    if (f < 0.0f) {
                                        if (nl < STASH) pL[nl++] = f;
                                        else { unsigned o = atomicAdd(&s_u[1], 1u); if (o < OVF) ovfL[o] = f; }
                                    } else {
                                        if (nh < STASH) pH[nh++] = f;
                                        else { unsigned o = atomicAdd(&s_u[2], 1u); if (o < OVF) ovfH[o] = f; }
                                    }
                                }
                            }
                        }
                    }
                }
            } else {
                // general two-compare fallback
                float w1 = g_win[slice][0];
                float w2 = g_win[slice][1];
                #pragma unroll 4
                for (int k = 0; k < GCHUNK / 4 / 256; k++) {
                    float4 v = xs[tid + k * 256];
                    float vv[4] = {v.x, v.y, v.z, v.w};
                    #pragma unroll
                    for (int c = 0; c < 4; c++) {
                        float f = vv[c];
                        if (f < w1) {
                            if (nl < STASH) pL[nl++] = f;
                            else { unsigned o = atomicAdd(&s_u[1], 1u); if (o < OVF) ovfL[o] = f; }
                        }
                        if (f >= w2) {
                            if (nh < STASH) pH[nh++] = f;
                            else { unsigned o = atomicAdd(&s_u[2], 1u); if (o < OVF) ovfH[o] = f; }
                        }
                    }
                }
            }
        }

        // block exclusive scan of stash counts
        unsigned cumL = nl, cumH = nh;
        #pragma unroll
        for (int o = 1; o < 32; o <<= 1) {
            unsigned tL = __shfl_up_sync(0xffffffffu, cumL, o);
            unsigned tH = __shfl_up_sync(0xffffffffu, cumH, o);
            if (lane >= o) { cumL += tL; cumH += tH; }
        }
        if (lane == 31) { wsumL[wrp] = cumL; wsumH[wrp] = cumH; }
        __syncthreads();

        if (tid == 0) {
            unsigned aL = 0, aH = 0;
            #pragma unroll
            for (int w = 0; w < 8; w++) {
                unsigned tL = wsumL[w], tH = wsumH[w];
                wsumL[w] = aL; wsumH[w] = aH;
                aL += tL; aH += tH;
            }
            unsigned ovl = s_u[1] < OVF ? s_u[1] : OVF;
            unsigned ovh = s_u[2] < OVF ? s_u[2] : OVF;
            s_u[1] = ovl; s_u[2] = ovh;
            s_u[7] = aL; s_u[8] = aH;
            s_u[5] = atomicAdd(&g_ncand[slice][0], aL + ovl);
            s_u[6] = atomicAdd(&g_ncand[slice][1], aH + ovh);
        }
        __syncthreads();

        unsigned offL = s_u[5] + wsumL[wrp] + cumL - nl;
        unsigned offH = s_u[6] + wsumH[wrp] + cumH - nh;
        for (unsigned j = 0; j < nl; j++) {
            unsigned gi = offL + j;
            if (gi < CAND_MAX) g_cand[slice][0][gi] = pL[j];
        }
        for (unsigned j = 0; j < nh; j++) {
            unsigned gi = offH + j;
            if (gi < CAND_MAX) g_cand[slice][1][gi] = pH[j];
        }
        for (unsigned j = tid; j < s_u[1]; j += 256) {
            unsigned gi = s_u[5] + s_u[7] + j;
            if (gi < CAND_MAX) g_cand[slice][0][gi] = ovfL[j];
        }
        for (unsigned j = tid; j < s_u[2]; j += 256) {
            unsigned gi = s_u[6] + s_u[8] + j;
            if (gi < CAND_MAX) g_cand[slice][1][gi] = ovfH[j];
        }

        // publish + last-block select
        __threadfence();
        __syncthreads();
        if (tid == 0) s_u[9] = atomicAdd(&g_done[slice], 1u);
        __syncthreads();
        if (s_u[9] == GBLK - 1) {
            __threadfence();   // acquire all gather blocks' writes
            unsigned* hist  = (unsigned*)stL;
            unsigned* tsum  = (unsigned*)stH;
            unsigned* red_u = (unsigned*)stH + 256;
            do_select(slice, 0, hist, tsum, red_u, &s_u[10]);
            __syncthreads();
            do_select(slice, 1, hist, tsum, red_u, &s_u[10]);
            __threadfence();
            __syncthreads();
            if (tid == 0) atomicExch(&g_flag[slice], 1u);
        }
    } else {
        // ---------------- normalize role (forward order) ----------------
        unsigned nt = ticket - gather_total;
        int slice = (int)(nt / NBLKN);
        int part  = (int)(nt % NBLKN);

        if (tid == 0) {
            unsigned ns = 64;
            while (poll_u32(&g_flag[slice]) == 0u) {
                __nanosleep(ns);
                if (ns < 2048) ns <<= 1;
            }
            __threadfence();
            s_q[0] = __ldcg(&g_q[slice][0]);
            s_q[1] = __ldcg(&g_q[slice][1]);
        }
        __syncthreads();
        float vmin = s_q[0], vmax = s_q[1];
        float a = 1.0f / (vmax - vmin + 1e-8f);
        float b = -vmin * a;

        size_t base = (size_t)slice * N_PER + (size_t)part * NCHUNK;
        const float4* xi = (const float4*)(x + base);
        float4* xo = (float4*)(out + base);
        const int NV = NCHUNK / 4;       // 2048
        #pragma unroll 4
        for (int i = tid; i < NV; i += 256) {
            float4 v = __ldcg(&xi[i]);
            v.x = __saturatef(fmaf(v.x, a, b));
            v.y = __saturatef(fmaf(v.y, a, b));
            v.z = __saturatef(fmaf(v.z, a, b));
            v.w = __saturatef(fmaf(v.w, a, b));
            __stcs(&xo[i], v);               // streaming store
        }
    }
}

extern "C" void kernel_launch(void* const* d_in, const int* in_sizes, int n_in,
                              void* d_out, int out_size) {
    const float* x = (const float*)d_in[0];
    float* out = (float*)d_out;
    int slices = out_size / N_PER;
    if (slices > MAX_SLICES) slices = MAX_SLICES;
    if (slices < 1) return;

    sample_kernel<<<slices, 256>>>(x);
    mega_kernel<<<slices * TPS, 256>>>(x, out);
}

// round 15
// speedup vs baseline: 1.6310x; 1.1296x over previous
#include <cuda_runtime.h>
#include <stdint.h>

// Problem geometry (x: (32, 7, 512, 512) fp32; per-(B,C) slice quantile over H*W)
#define MAX_SLICES 224
#define N_PER      262144           // 512*512
#define M_SAMP     4096
#define NGROUP     512              // sample groups of 8 contiguous floats
#define CAND_MAX   32768

// Sample-rank brackets among 4096 sorted samples.
#define R_LO 100
#define R_HI 3995

#define NBIN 4096                   // top-12 bits of monotone key

// work partition (two-phase tickets, forward order — R11 skeleton)
#define GBLK   32                   // gather chunks per slice
#define GCHUNK (N_PER / GBLK)       // 8192 elements
#define NBLKN  32                   // normalize chunks per slice
#define NCHUNK (N_PER / NBLKN)      // 8192 elements
#define TPS    (GBLK + NBLKN)
#define STASH  10                   // per-thread stash (mean ~0.8 of 32 elems/side)
#define SROW   (STASH + 1)          // padded row, conflict-free
#define OVF    512                  // per-block overflow fallback

// ---- static device scratch (no allocations allowed) ----
__device__ float    g_lo[MAX_SLICES];        // low-tail cut (candidates: f <  lo)
__device__ float    g_hi[MAX_SLICES];        // high-tail cut (candidates: f >= hi)
__device__ unsigned g_ncand[MAX_SLICES][2];
__device__ float    g_cand[MAX_SLICES][2][CAND_MAX];
__device__ float    g_q[MAX_SLICES][2];
__device__ unsigned g_ticket;
__device__ unsigned g_done[MAX_SLICES];
__device__ unsigned g_flag[MAX_SLICES];

// Monotone float <-> uint key
__device__ __forceinline__ unsigned fkey(float f) {
    unsigned u = __float_as_uint(f);
    return (u & 0x80000000u) ? ~u : (u | 0x80000000u);
}
__device__ __forceinline__ float funkey(unsigned k) {
    return (k & 0x80000000u) ? __uint_as_float(k & 0x7FFFFFFFu)
                             : __uint_as_float(~k);
}
__device__ __forceinline__ unsigned poll_u32(const unsigned* p) {
    unsigned v;
    asm volatile("ld.global.cg.u32 %0, [%1];" : "=r"(v) : "l"(p) : "memory");
    return v;
}

// ============================================================
// Kernel 1: per-slice sample histogram -> tail cuts lo / hi
// ============================================================
__global__ void sample_kernel(const float* __restrict__ x) {
    __shared__ unsigned hist[NBIN];
    __shared__ unsigned toff[257];
    __shared__ unsigned sh_bin[2];
    __shared__ unsigned wsum[8];

    int slice = blockIdx.x;
    int tid = threadIdx.x;
    const float* xs = x + (size_t)slice * N_PER;

    if (slice == 0 && tid == 0) g_ticket = 0;

    for (int i = tid; i < NBIN; i += 256) hist[i] = 0;
    __syncthreads();

    #pragma unroll
    for (int g = tid; g < NGROUP; g += 256) {
        const float4* gp = (const float4*)(xs + (size_t)g * (N_PER / NGROUP));
        #pragma unroll
        for (int j = 0; j < 2; j++) {
            float4 v = gp[j];
            atomicAdd(&hist[fkey(v.x) >> 20], 1u);
            atomicAdd(&hist[fkey(v.y) >> 20], 1u);
            atomicAdd(&hist[fkey(v.z) >> 20], 1u);
            atomicAdd(&hist[fkey(v.w) >> 20], 1u);
        }
    }
    __syncthreads();

    unsigned s = 0;
    #pragma unroll
    for (int b = 0; b < 16; b++) s += hist[tid * 16 + b];

    int lane = tid & 31, wrp = tid >> 5;
    unsigned cum = s;
    #pragma unroll
    for (int o = 1; o < 32; o <<= 1) {
        unsigned t = __shfl_up_sync(0xffffffffu, cum, o);
        if (lane >= o) cum += t;
    }
    if (lane == 31) wsum[wrp] = cum;
    __syncthreads();
    if (tid == 0) {
        unsigned acc = 0;
        #pragma unroll
        for (int w = 0; w < 8; w++) { unsigned t = wsum[w]; wsum[w] = acc; acc += t; }
    }
    __syncthreads();
    toff[tid] = wsum[wrp] + cum - s;
    if (tid == 255) toff[256] = M_SAMP;
    __syncthreads();

    const int ranks[2] = {R_LO, R_HI};
    if (tid < 2) {
        unsigned R = (unsigned)ranks[tid];
        int lo = 0, hi = 256;
        while (hi - lo > 1) {
            int mid = (lo + hi) >> 1;
            if (toff[mid] <= R) lo = mid; else hi = mid;
        }
        unsigned acc = toff[lo];
        int bin = lo * 16;
        #pragma unroll
        for (int b = 0; b < 16; b++) {
            unsigned h = hist[lo * 16 + b];
            if (acc + h > R) { bin = lo * 16 + b; break; }
            acc += h;
        }
        sh_bin[tid] = (unsigned)bin;
    }
    __syncthreads();

    if (tid == 0) {
        float w1 = funkey((sh_bin[0] + 1u) << 20);   // upper edge of lo-tail bin
        float w2 = funkey(sh_bin[1] << 20);          // lower edge of hi-tail bin
        // symmetric tightening when sign-split: lo = -t, hi = t, t = min(-w1, w2)
        // ({f < -t} superset of certified {f < w1}; mirror for hi) — selection exact.
        if (w1 < 0.0f && w2 > 0.0f) {
            float t = fminf(-w1, w2);
            g_lo[slice] = -t;
            g_hi[slice] =  t;
        } else {
            g_lo[slice] = w1;
            g_hi[slice] = w2;
        }
        g_ncand[slice][0] = 0; g_ncand[slice][1] = 0;
        g_done[slice] = 0;
        g_flag[slice] = 0;
    }
}

// ============================================================
// Inline select: exact radix-select among candidates of (slice, w).
// w=0: candidates are ALL f < lo  -> base count 0.
// w=1: candidates are ALL f >= hi -> base = N - n.
// ============================================================
__device__ void do_select(int slice, int w, unsigned* hist, unsigned* tsum,
                          unsigned* red_u, volatile unsigned* sh2) {
    int tid = threadIdx.x;
    unsigned n_raw = g_ncand[slice][w];
    unsigned n = n_raw > CAND_MAX ? CAND_MAX : n_raw;
    unsigned cnt = (w == 0) ? 0u : (unsigned)N_PER - n_raw;

    double pos  = (w == 0) ? 0.01 * (double)(N_PER - 1) : 0.99 * (double)(N_PER - 1);
    long long K = (long long)pos;
    double frac = pos - (double)K;

    if (n < 2) {
        if (tid == 0) g_q[slice][w] = (n == 1) ? g_cand[slice][w][0] : 0.0f;
        return;
    }
    long long rl = K - (long long)cnt;
    if (rl < 0) rl = 0;
    if (rl > (long long)n - 2) rl = (long long)n - 2;
    int r = (int)rl;
    const float* cand = g_cand[slice][w];

    unsigned prefix = 0, pmask = 0;
    int rrem = r;
    const int shifts[3] = {21, 10, 0};
    const int bitsv[3]  = {11, 11, 10};
    #pragma unroll
    for (int p = 0; p < 3; p++) {
        int shift = shifts[p];
        unsigned nb = 1u << bitsv[p];
        unsigned dmask = nb - 1u;
        unsigned per = nb / 256;
        for (unsigned i = tid; i < 2048; i += 256) hist[i] = 0;
        __syncthreads();
        for (unsigned i = tid; i < n; i += 256) {
            unsigned u = fkey(cand[i]);
            if ((u & pmask) == prefix)
                atomicAdd(&hist[(u >> shift) & dmask], 1u);
        }
        __syncthreads();
        unsigned s = 0;
        for (unsigned q2 = 0; q2 < per; q2++) s += hist[tid * per + q2];
        tsum[tid] = s;
        __syncthreads();

        if (tid < 32) {
            unsigned part[8];
            unsigned ls = 0;
            #pragma unroll
            for (int j = 0; j < 8; j++) { part[j] = tsum[tid * 8 + j]; ls += part[j]; }
            unsigned cum = ls;
            #pragma unroll
            for (int o = 1; o < 32; o <<= 1) {
                unsigned t = __shfl_up_sync(0xffffffffu, cum, o);
                if (tid >= o) cum += t;
            }
            unsigned excl = cum - ls;
            unsigned ball = __ballot_sync(0xffffffffu, cum > (unsigned)rrem);
            int cross = __ffs(ball) - 1;
            if (tid == cross) {
                unsigned acc = excl;
                int tc = tid * 8;
                #pragma unroll
                for (int j = 0; j < 8; j++) {
                    if (acc + part[j] > (unsigned)rrem) { tc = tid * 8 + j; break; }
                    acc += part[j];
                }
                unsigned d = (unsigned)tc * per;
                for (unsigned b = 0; b < per; b++) {
                    unsigned h = hist[tc * per + b];
                    if (acc + h > (unsigned)rrem) { d = (unsigned)tc * per + b; break; }
                    acc += h;
                }
                sh2[0] = d;
                sh2[1] = (unsigned)rrem - acc;
            }
        }
        __syncthreads();
        prefix |= sh2[0] << shift;
        pmask  |= dmask << shift;
        rrem = (int)sh2[1];
        __syncthreads();
    }
    unsigned v0key = prefix;

    unsigned cle = 0, mgt = 0xFFFFFFFFu;
    for (unsigned i = tid; i < n; i += 256) {
        unsigned u = fkey(cand[i]);
        cle += (u <= v0key);
        if (u > v0key && u < mgt) mgt = u;
    }
    red_u[tid] = cle; __syncthreads();
    for (int o = 128; o; o >>= 1) {
        if (tid < o) red_u[tid] += red_u[tid + o];
        __syncthreads();
    }
    unsigned cle_tot = red_u[0]; __syncthreads();
    red_u[tid] = mgt; __syncthreads();
    for (int o = 128; o; o >>= 1) {
        if (tid < o) red_u[tid] = (red_u[tid + o] < red_u[tid]) ? red_u[tid + o] : red_u[tid];
        __syncthreads();
    }
    unsigned mgt_tot = red_u[0];
    __syncthreads();

    if (tid == 0) {
        unsigned v1key = (cle_tot >= (unsigned)(r + 2)) ? v0key
                       : ((mgt_tot != 0xFFFFFFFFu) ? mgt_tot : v0key);
        double v0 = (double)funkey(v0key);
        double v1 = (double)funkey(v1key);
        g_q[slice][w] = (float)(v0 + frac * (v1 - v0));
    }
}

// ============================================================
// Mega kernel (R11 skeleton): gather tickets first, then normalize.
// Gather hot loop is FULLY PREDICATED (no branches -> no BSSY/BSYNC):
// @p STS / @p IADD only. Overflow handled by a rare post-loop rescan.
// ============================================================
__global__ void __launch_bounds__(256) mega_kernel(const float* __restrict__ x,
                                                   float* __restrict__ out) {
    __shared__ float stL[256 * SROW];        // 11.3 KB
    __shared__ float stH[256 * SROW];        // 11.3 KB (aliased in select)
    __shared__ float ovfL[OVF], ovfH[OVF];   // 4 KB
    __shared__ unsigned s_u[16];
    __shared__ unsigned wsumL[8], wsumH[8];
    __shared__ float s_q[2];

    int tid = threadIdx.x;
    int lane = tid & 31, wrp = tid >> 5;
    int slices = gridDim.x / TPS;
    unsigned gather_total = (unsigned)(GBLK * slices);

    if (tid == 0) {
        s_u[0] = atomicAdd(&g_ticket, 1u);
        s_u[1] = 0; s_u[2] = 0;
    }
    __syncthreads();
    unsigned ticket = s_u[0];

    if (ticket < gather_total) {
        // ---------------- gather role ----------------
        int slice = (int)(ticket / GBLK);
        int part  = (int)(ticket % GBLK);
        const float4* xs = (const float4*)(x + (size_t)slice * N_PER
                                             + (size_t)part * GCHUNK);
        float lo = g_lo[slice];
        float hi = g_hi[slice];

        float* pL = &stL[tid * SROW];
        float* pH = &stH[tid * SROW];
        unsigned nl = 0, nh = 0;

        // branch-free hot loop: 8 float4/thread, batched 4 for MLP
        #pragma unroll
        for (int kb = 0; kb < 2; kb++) {
            float4 r[4];
            #pragma unroll
            for (int k = 0; k < 4; k++)
                r[k] = xs[tid + (kb * 4 + k) * 256];
            #pragma unroll
            for (int k = 0; k < 4; k++) {
                float vv[4] = {r[k].x, r[k].y, r[k].z, r[k].w};
                #pragma unroll
                for (int c = 0; c < 4; c++) {
                    float f = vv[c];
                    bool cl = (f < lo);
                    bool ch = (f >= hi);
                    if (cl & (nl < STASH)) pL[nl] = f;   // @p STS
                    nl += cl;                            // predicated IADD
                    if (ch & (nh < STASH)) pH[nh] = f;
                    nh += ch;
                }
            }
        }

        // rare overflow rescan (P ~ 1e-9/thread): recover dropped candidates
        if (__any_sync(0xffffffffu, (nl > STASH) | (nh > STASH))) {
            if ((nl > STASH) | (nh > STASH)) {
                unsigned cnl = 0, cnh = 0;
                for (int k = 0; k < GCHUNK / 4 / 256; k++) {
                    float4 v = xs[tid + k * 256];
                    float vv[4] = {v.x, v.y, v.z, v.w};
                    for (int c = 0; c < 4; c++) {
                        float f = vv[c];
                        if (f < lo) {
                            if (cnl >= STASH) {
                                unsigned o = atomicAdd(&s_u[1], 1u);
                                if (o < OVF) ovfL[o] = f;
                            }
                            cnl++;
                        }
                        if (f >= hi) {
                            if (cnh >= STASH) {
                                unsigned o = atomicAdd(&s_u[2], 1u);
                                if (o < OVF) ovfH[o] = f;
                            }
                            cnh++;
                        }
                    }
                }
            }
            nl = nl > STASH ? STASH : nl;
            nh = nh > STASH ? STASH : nh;
        }

        // block exclusive scan of stash counts
        unsigned cumL = nl, cumH = nh;
        #pragma unroll
        for (int o = 1; o < 32; o <<= 1) {
            unsigned tL = __shfl_up_sync(0xffffffffu, cumL, o);
            unsigned tH = __shfl_up_sync(0xffffffffu, cumH, o);
            if (lane >= o) { cumL += tL; cumH += tH; }
        }
        if (lane == 31) { wsumL[wrp] = cumL; wsumH[wrp] = cumH; }
        __syncthreads();

        if (tid == 0) {
            unsigned aL = 0, aH = 0;
            #pragma unroll
            for (int w = 0; w < 8; w++) {
                unsigned tL = wsumL[w], tH = wsumH[w];
                wsumL[w] = aL; wsumH[w] = aH;
                aL += tL; aH += tH;
            }
            unsigned ovl = s_u[1] < OVF ? s_u[1] : OVF;
            unsigned ovh = s_u[2] < OVF ? s_u[2] : OVF;
            s_u[1] = ovl; s_u[2] = ovh;
            s_u[7] = aL; s_u[8] = aH;
            s_u[5] = atomicAdd(&g_ncand[slice][0], aL + ovl);
            s_u[6] = atomicAdd(&g_ncand[slice][1], aH + ovh);
        }
        __syncthreads();

        unsigned offL = s_u[5] + wsumL[wrp] + cumL - nl;
        unsigned offH = s_u[6] + wsumH[wrp] + cumH - nh;
        for (unsigned j = 0; j < nl; j++) {
            unsigned gi = offL + j;
            if (gi < CAND_MAX) g_cand[slice][0][gi] = pL[j];
        }
        for (unsigned j = 0; j < nh; j++) {
            unsigned gi = offH + j;
            if (gi < CAND_MAX) g_cand[slice][1][gi] = pH[j];
        }
        for (unsigned j = tid; j < s_u[1]; j += 256) {
            unsigned gi = s_u[5] + s_u[7] + j;
            if (gi < CAND_MAX) g_cand[slice][0][gi] = ovfL[j];
        }
        for (unsigned j = tid; j < s_u[2]; j += 256) {
            unsigned gi = s_u[6] + s_u[8] + j;
            if (gi < CAND_MAX) g_cand[slice][1][gi] = ovfH[j];
        }

        // publish + last-block select
        __threadfence();
        __syncthreads();
        if (tid == 0) s_u[9] = atomicAdd(&g_done[slice], 1u);
        __syncthreads();
        if (s_u[9] == GBLK - 1) {
            __threadfence();   // acquire all gather blocks' writes
            unsigned* hist  = (unsigned*)stL;
            unsigned* tsum  = (unsigned*)stH;
            unsigned* red_u = (unsigned*)stH + 256;
            do_select(slice, 0, hist, tsum, red_u, &s_u[10]);
            __syncthreads();
            do_select(slice, 1, hist, tsum, red_u, &s_u[10]);
            __threadfence();
            __syncthreads();
            if (tid == 0) atomicExch(&g_flag[slice], 1u);
        }
    } else {
        // ---------------- normalize role (forward order) ----------------
        unsigned nt = ticket - gather_total;
        int slice = (int)(nt / NBLKN);
        int part  = (int)(nt % NBLKN);

        if (tid == 0) {
            unsigned ns = 64;
            while (poll_u32(&g_flag[slice]) == 0u) {
                __nanosleep(ns);
                if (ns < 2048) ns <<= 1;
            }
            __threadfence();
            s_q[0] = __ldcg(&g_q[slice][0]);
            s_q[1] = __ldcg(&g_q[slice][1]);
        }
        __syncthreads();
        float vmin = s_q[0], vmax = s_q[1];
        float a = 1.0f / (vmax - vmin + 1e-8f);
        float b = -vmin * a;

        size_t base = (size_t)slice * N_PER + (size_t)part * NCHUNK;
        const float4* xi = (const float4*)(x + base);
        float4* xo = (float4*)(out + base);
        const int NV = NCHUNK / 4;       // 2048
        #pragma unroll 4
        for (int i = tid; i < NV; i += 256) {
            float4 v = __ldcg(&xi[i]);
            v.x = __saturatef(fmaf(v.x, a, b));
            v.y = __saturatef(fmaf(v.y, a, b));
            v.z = __saturatef(fmaf(v.z, a, b));
            v.w = __saturatef(fmaf(v.w, a, b));
            __stcs(&xo[i], v);               // streaming store
        }
    }
}

extern "C" void kernel_launch(void* const* d_in, const int* in_sizes, int n_in,
                              void* d_out, int out_size) {
    const float* x = (const float*)d_in[0];
    float* out = (float*)d_out;
    int slices = out_size / N_PER;
    if (slices > MAX_SLICES) slices = MAX_SLICES;
    if (slices < 1) return;

    sample_kernel<<<slices, 256>>>(x);
    mega_kernel<<<slices * TPS, 256>>>(x, out);
}

// round 16
// speedup vs baseline: 1.6427x; 1.0072x over previous
#include <cuda_runtime.h>
#include <stdint.h>

// Problem geometry (x: (32, 7, 512, 512) fp32; per-(B,C) slice quantile over H*W)
#define MAX_SLICES 224
#define N_PER      262144           // 512*512
#define M_SAMP     4096
#define NGROUP     512              // sample groups of 8 contiguous floats
#define CAND_MAX   32768

// Sample-rank brackets among 4096 sorted samples.
#define R_LO 100
#define R_HI 3995

#define NBIN 4096                   // top-12 bits of monotone key

// work partition (two-phase tickets, forward order)
#define GBLK   32                   // gather chunks per slice
#define GCHUNK (N_PER / GBLK)       // 8192 elements
#define NBLKN  32                   // normalize chunks per slice
#define NCHUNK (N_PER / NBLKN)      // 8192 elements
#define TPS    (GBLK + NBLKN)
#define STASH  12                   // combined per-thread stash (mean ~1.6 of 32)
#define SROW   (STASH + 1)          // padded row, conflict-free
#define OVF    512                  // per-block overflow fallback (per side)

// ---- static device scratch (no allocations allowed) ----
__device__ float    g_lo[MAX_SLICES];        // low-tail predicate cut
__device__ float    g_hi[MAX_SLICES];        // high-tail predicate cut (= t in sym mode)
__device__ float    g_cut[MAX_SLICES];       // classification cut (0 in sym mode)
__device__ int      g_sym[MAX_SLICES];       // 1 = symmetric |f|>=t single-FSETP mode
__device__ unsigned g_ncand[MAX_SLICES][2];
__device__ float    g_cand[MAX_SLICES][2][CAND_MAX];
__device__ float    g_q[MAX_SLICES][2];
__device__ unsigned g_ticket;
__device__ unsigned g_done[MAX_SLICES];
__device__ unsigned g_flag[MAX_SLICES];

// Monotone float <-> uint key
__device__ __forceinline__ unsigned fkey(float f) {
    unsigned u = __float_as_uint(f);
    return (u & 0x80000000u) ? ~u : (u | 0x80000000u);
}
__device__ __forceinline__ float funkey(unsigned k) {
    return (k & 0x80000000u) ? __uint_as_float(k & 0x7FFFFFFFu)
                             : __uint_as_float(~k);
}
__device__ __forceinline__ unsigned poll_u32(const unsigned* p) {
    unsigned v;
    asm volatile("ld.global.cg.u32 %0, [%1];" : "=r"(v) : "l"(p) : "memory");
    return v;
}

// ============================================================
// Kernel 1: per-slice sample histogram -> tail cuts
// ============================================================
__global__ void sample_kernel(const float* __restrict__ x) {
    __shared__ unsigned hist[NBIN];
    __shared__ unsigned toff[257];
    __shared__ unsigned sh_bin[2];
    __shared__ unsigned wsum[8];

    int slice = blockIdx.x;
    int tid = threadIdx.x;
    const float* xs = x + (size_t)slice * N_PER;

    if (slice == 0 && tid == 0) g_ticket = 0;

    for (int i = tid; i < NBIN; i += 256) hist[i] = 0;
    __syncthreads();

    #pragma unroll
    for (int g = tid; g < NGROUP; g += 256) {
        const float4* gp = (const float4*)(xs + (size_t)g * (N_PER / NGROUP));
        #pragma unroll
        for (int j = 0; j < 2; j++) {
            float4 v = gp[j];
            atomicAdd(&hist[fkey(v.x) >> 20], 1u);
            atomicAdd(&hist[fkey(v.y) >> 20], 1u);
            atomicAdd(&hist[fkey(v.z) >> 20], 1u);
            atomicAdd(&hist[fkey(v.w) >> 20], 1u);
        }
    }
    __syncthreads();

    unsigned s = 0;
    #pragma unroll
    for (int b = 0; b < 16; b++) s += hist[tid * 16 + b];

    int lane = tid & 31, wrp = tid >> 5;
    unsigned cum = s;
    #pragma unroll
    for (int o = 1; o < 32; o <<= 1) {
        unsigned t = __shfl_up_sync(0xffffffffu, cum, o);
        if (lane >= o) cum += t;
    }
    if (lane == 31) wsum[wrp] = cum;
    __syncthreads();
    if (tid == 0) {
        unsigned acc = 0;
        #pragma unroll
        for (int w = 0; w < 8; w++) { unsigned t = wsum[w]; wsum[w] = acc; acc += t; }
    }
    __syncthreads();
    toff[tid] = wsum[wrp] + cum - s;
    if (tid == 255) toff[256] = M_SAMP;
    __syncthreads();

    const int ranks[2] = {R_LO, R_HI};
    if (tid < 2) {
        unsigned R = (unsigned)ranks[tid];
        int lo = 0, hi = 256;
        while (hi - lo > 1) {
            int mid = (lo + hi) >> 1;
            if (toff[mid] <= R) lo = mid; else hi = mid;
        }
        unsigned acc = toff[lo];
        int bin = lo * 16;
        #pragma unroll
        for (int b = 0; b < 16; b++) {
            unsigned h = hist[lo * 16 + b];
            if (acc + h > R) { bin = lo * 16 + b; break; }
            acc += h;
        }
        sh_bin[tid] = (unsigned)bin;
    }
    __syncthreads();

    if (tid == 0) {
        float w1 = funkey((sh_bin[0] + 1u) << 20);   // upper edge of lo-tail bin
        float w2 = funkey(sh_bin[1] << 20);          // lower edge of hi-tail bin
        if (w1 < 0.0f && w2 > 0.0f) {
            // symmetric mode: candidates = {|f| >= t}; low = {f <= -t} (prefix),
            // high = {f >= t} (suffix); classify by sign (cut = 0).
            float t = fminf(-w1, w2);
            g_lo[slice] = -t;
            g_hi[slice] =  t;
            g_cut[slice] = 0.0f;
            g_sym[slice] = 1;
        } else {
            g_lo[slice] = w1;
            g_hi[slice] = w2;
            g_cut[slice] = w1;
            g_sym[slice] = 0;
        }
        g_ncand[slice][0] = 0; g_ncand[slice][1] = 0;
        g_done[slice] = 0;
        g_flag[slice] = 0;
    }
}

// ============================================================
// Inline select: exact radix-select among candidates of (slice, w).
// w=0: candidates are ALL f below the low cut  -> base count 0.
// w=1: candidates are ALL f at/above high cut  -> base = N - n.
// ============================================================
__device__ void do_select(int slice, int w, unsigned* hist, unsigned* tsum,
                          unsigned* red_u, volatile unsigned* sh2) {
    int tid = threadIdx.x;
    unsigned n_raw = g_ncand[slice][w];
    unsigned n = n_raw > CAND_MAX ? CAND_MAX : n_raw;
    unsigned cnt = (w == 0) ? 0u : (unsigned)N_PER - n_raw;

    double pos  = (w == 0) ? 0.01 * (double)(N_PER - 1) : 0.99 * (double)(N_PER - 1);
    long long K = (long long)pos;
    double frac = pos - (double)K;

    if (n < 2) {
        if (tid == 0) g_q[slice][w] = (n == 1) ? g_cand[slice][w][0] : 0.0f;
        return;
    }
    long long rl = K - (long long)cnt;
    if (rl < 0) rl = 0;
    if (rl > (long long)n - 2) rl = (long long)n - 2;
    int r = (int)rl;
    const float* cand = g_cand[slice][w];

    unsigned prefix = 0, pmask = 0;
    int rrem = r;
    const int shifts[3] = {21, 10, 0};
    const int bitsv[3]  = {11, 11, 10};
    #pragma unroll
    for (int p = 0; p < 3; p++) {
        int shift = shifts[p];
        unsigned nb = 1u << bitsv[p];
        unsigned dmask = nb - 1u;
        unsigned per = nb / 256;
        for (unsigned i = tid; i < 2048; i += 256) hist[i] = 0;
        __syncthreads();
        for (unsigned i = tid; i < n; i += 256) {
            unsigned u = fkey(cand[i]);
            if ((u & pmask) == prefix)
                atomicAdd(&hist[(u >> shift) & dmask], 1u);
        }
        __syncthreads();
        unsigned s = 0;
        for (unsigned q2 = 0; q2 < per; q2++) s += hist[tid * per + q2];
        tsum[tid] = s;
        __syncthreads();

        if (tid < 32) {
            unsigned part[8];
            unsigned ls = 0;
            #pragma unroll
            for (int j = 0; j < 8; j++) { part[j] = tsum[tid * 8 + j]; ls += part[j]; }
            unsigned cum = ls;
            #pragma unroll
            for (int o = 1; o < 32; o <<= 1) {
                unsigned t = __shfl_up_sync(0xffffffffu, cum, o);
                if (tid >= o) cum += t;
            }
            unsigned excl = cum - ls;
            unsigned ball = __ballot_sync(0xffffffffu, cum > (unsigned)rrem);
            int cross = __ffs(ball) - 1;
            if (tid == cross) {
                unsigned acc = excl;
                int tc = tid * 8;
                #pragma unroll
                for (int j = 0; j < 8; j++) {
                    if (acc + part[j] > (unsigned)rrem) { tc = tid * 8 + j; break; }
                    acc += part[j];
                }
                unsigned d = (unsigned)tc * per;
                for (unsigned b = 0; b < per; b++) {
                    unsigned h = hist[tc * per + b];
                    if (acc + h > (unsigned)rrem) { d = (unsigned)tc * per + b; break; }
                    acc += h;
                }
                sh2[0] = d;
                sh2[1] = (unsigned)rrem - acc;
            }
        }
        __syncthreads();
        prefix |= sh2[0] << shift;
        pmask  |= dmask << shift;
        rrem = (int)sh2[1];
        __syncthreads();
    }
    unsigned v0key = prefix;

    unsigned cle = 0, mgt = 0xFFFFFFFFu;
    for (unsigned i = tid; i < n; i += 256) {
        unsigned u = fkey(cand[i]);
        cle += (u <= v0key);
        if (u > v0key && u < mgt) mgt = u;
    }
    red_u[tid] = cle; __syncthreads();
    for (int o = 128; o; o >>= 1) {
        if (tid < o) red_u[tid] += red_u[tid + o];
        __syncthreads();
    }
    unsigned cle_tot = red_u[0]; __syncthreads();
    red_u[tid] = mgt; __syncthreads();
    for (int o = 128; o; o >>= 1) {
        if (tid < o) red_u[tid] = (red_u[tid + o] < red_u[tid]) ? red_u[tid + o] : red_u[tid];
        __syncthreads();
    }
    unsigned mgt_tot = red_u[0];
    __syncthreads();

    if (tid == 0) {
        unsigned v1key = (cle_tot >= (unsigned)(r + 2)) ? v0key
                       : ((mgt_tot != 0xFFFFFFFFu) ? mgt_tot : v0key);
        double v0 = (double)funkey(v0key);
        double v1 = (double)funkey(v1key);
        g_q[slice][w] = (float)(v0 + frac * (v1 - v0));
    }
}

// ============================================================
// Mega kernel: gather tickets first, then normalize tickets.
// Gather hot loop: ONE predicate + ONE @p STS + ONE IADD per
// element into a single combined stash; classification into
// low/high happens post-loop on the ~1.6 stashed elems/thread.
// ============================================================
__global__ void __launch_bounds__(256) mega_kernel(const float* __restrict__ x,
                                                   float* __restrict__ out) {
    __shared__ float stS[256 * SROW];        // 13.3 KB combined stash
    __shared__ float ovfL[OVF], ovfH[OVF];   // 4 KB
    __shared__ unsigned s_u[16];
    __shared__ unsigned wsumL[8], wsumH[8];
    __shared__ float s_q[2];

    int tid = threadIdx.x;
    int lane = tid & 31, wrp = tid >> 5;
    int slices = gridDim.x / TPS;
    unsigned gather_total = (unsigned)(GBLK * slices);

    if (tid == 0) {
        s_u[0] = atomicAdd(&g_ticket, 1u);
        s_u[1] = 0; s_u[2] = 0;
    }
    __syncthreads();
    unsigned ticket = s_u[0];

    if (ticket < gather_total) {
        // ---------------- gather role ----------------
        int slice = (int)(ticket / GBLK);
        int part  = (int)(ticket % GBLK);
        const float4* xs = (const float4*)(x + (size_t)slice * N_PER
                                             + (size_t)part * GCHUNK);
        float lo  = g_lo[slice];
        float hi  = g_hi[slice];
        float cut = g_cut[slice];
        int   sym = g_sym[slice];

        float* pS = &stS[tid * SROW];
        unsigned ns = 0;

        if (sym) {
            float t = hi;
            // 3 issues per element: FSETP(|f|,t), @p STS, IADD
            #pragma unroll
            for (int kb = 0; kb < 2; kb++) {
                float4 r[4];
                #pragma unroll
                for (int k = 0; k < 4; k++)
                    r[k] = xs[tid + (kb * 4 + k) * 256];
                #pragma unroll
                for (int k = 0; k < 4; k++) {
                    float vv[4] = {r[k].x, r[k].y, r[k].z, r[k].w};
                    #pragma unroll
                    for (int c = 0; c < 4; c++) {
                        float f = vv[c];
                        bool p = (fabsf(f) >= t);
                        if (p & (ns < STASH)) pS[ns] = f;
                        ns += p;
                    }
                }
            }
        } else {
            #pragma unroll
            for (int kb = 0; kb < 2; kb++) {
                float4 r[4];
                #pragma unroll
                for (int k = 0; k < 4; k++)
                    r[k] = xs[tid + (kb * 4 + k) * 256];
                #pragma unroll
                for (int k = 0; k < 4; k++) {
                    float vv[4] = {r[k].x, r[k].y, r[k].z, r[k].w};
                    #pragma unroll
                    for (int c = 0; c < 4; c++) {
                        float f = vv[c];
                        bool p = (f < lo) | (f >= hi);
                        if (p & (ns < STASH)) pS[ns] = f;
                        ns += p;
                    }
                }
            }
        }

        // rare overflow rescan: recover candidates with ordinal >= STASH
        if (__any_sync(0xffffffffu, ns > STASH)) {
            if (ns > STASH) {
                unsigned cn = 0;
                for (int k = 0; k < GCHUNK / 4 / 256; k++) {
                    float4 v = xs[tid + k * 256];
                    float vv[4] = {v.x, v.y, v.z, v.w};
                    for (int c = 0; c < 4; c++) {
                        float f = vv[c];
                        bool p = sym ? (fabsf(f) >= hi) : ((f < lo) | (f >= hi));
                        if (p) {
                            if (cn >= STASH) {
                                if (f < cut) {
                                    unsigned o = atomicAdd(&s_u[1], 1u);
                                    if (o < OVF) ovfL[o] = f;
                                } else {
                                    unsigned o = atomicAdd(&s_u[2], 1u);
                                    if (o < OVF) ovfH[o] = f;
                                }
                            }
                            cn++;
                        }
                    }
                }
            }
            ns = ns > STASH ? STASH : ns;
        }

        // classify stash: low iff f < cut
        unsigned nl = 0;
        for (unsigned j = 0; j < ns; j++) nl += (pS[j] < cut);
        unsigned nh = ns - nl;

        // block exclusive scan of per-side counts
        unsigned cumL = nl, cumH = nh;
        #pragma unroll
        for (int o = 1; o < 32; o <<= 1) {
            unsigned tL = __shfl_up_sync(0xffffffffu, cumL, o);
            unsigned tH = __shfl_up_sync(0xffffffffu, cumH, o);
            if (lane >= o) { cumL += tL; cumH += tH; }
        }
        if (lane == 31) { wsumL[wrp] = cumL; wsumH[wrp] = cumH; }
        __syncthreads();

        if (tid == 0) {
            unsigned aL = 0, aH = 0;
            #pragma unroll
            for (int w = 0; w < 8; w++) {
                unsigned tL = wsumL[w], tH = wsumH[w];
                wsumL[w] = aL; wsumH[w] = aH;
                aL += tL; aH += tH;
            }
            unsigned ovl = s_u[1] < OVF ? s_u[1] : OVF;
            unsigned ovh = s_u[2] < OVF ? s_u[2] : OVF;
            s_u[1] = ovl; s_u[2] = ovh;
            s_u[7] = aL; s_u[8] = aH;
            s_u[5] = atomicAdd(&g_ncand[slice][0], aL + ovl);
            s_u[6] = atomicAdd(&g_ncand[slice][1], aH + ovh);
        }
        __syncthreads();

        unsigned offL = s_u[5] + wsumL[wrp] + cumL - nl;
        unsigned offH = s_u[6] + wsumH[wrp] + cumH - nh;
        unsigned il = 0, ih = 0;
        for (unsigned j = 0; j < ns; j++) {
            float f = pS[j];
            if (f < cut) {
                unsigned gi = offL + il++;
                if (gi < CAND_MAX) g_cand[slice][0][gi] = f;
            } else {
                unsigned gi = offH + ih++;
                if (gi < CAND_MAX) g_cand[slice][1][gi] = f;
            }
        }
        for (unsigned j = tid; j < s_u[1]; j += 256) {
            unsigned gi = s_u[5] + s_u[7] + j;
            if (gi < CAND_MAX) g_cand[slice][0][gi] = ovfL[j];
        }
        for (unsigned j = tid; j < s_u[2]; j += 256) {
            unsigned gi = s_u[6] + s_u[8] + j;
            if (gi < CAND_MAX) g_cand[slice][1][gi] = ovfH[j];
        }

        // publish + last-block select
        __threadfence();
        __syncthreads();
        if (tid == 0) s_u[9] = atomicAdd(&g_done[slice], 1u);
        __syncthreads();
        if (s_u[9] == GBLK - 1) {
            __threadfence();   // acquire all gather blocks' writes
            unsigned* hist  = (unsigned*)stS;          // 8 KB of 13.3 KB
            unsigned* tsum  = (unsigned*)stS + 2048;
            unsigned* red_u = (unsigned*)stS + 2304;
            do_select(slice, 0, hist, tsum, red_u, &s_u[10]);
            __syncthreads();
            do_select(slice, 1, hist, tsum, red_u, &s_u[10]);
            __threadfence();
            __syncthreads();
            if (tid == 0) atomicExch(&g_flag[slice], 1u);
        }
    } else {
        // ---------------- normalize role (forward order) ----------------
        unsigned nt = ticket - gather_total;
        int slice = (int)(nt / NBLKN);
        int part  = (int)(nt % NBLKN);

        if (tid == 0) {
            unsigned w = 64;
            while (poll_u32(&g_flag[slice]) == 0u) {
                __nanosleep(w);
                if (w < 2048) w <<= 1;
            }
            __threadfence();
            s_q[0] = __ldcg(&g_q[slice][0]);
            s_q[1] = __ldcg(&g_q[slice][1]);
        }
        __syncthreads();
        float vmin = s_q[0], vmax = s_q[1];
        float a = 1.0f / (vmax - vmin + 1e-8f);
        float b = -vmin * a;

        size_t base = (size_t)slice * N_PER + (size_t)part * NCHUNK;
        const float4* xi = (const float4*)(x + base);
        float4* xo = (float4*)(out + base);
        const int NV = NCHUNK / 4;       // 2048
        #pragma unroll 4
        for (int i = tid; i < NV; i += 256) {
            float4 v = __ldcg(&xi[i]);
            v.x = __saturatef(fmaf(v.x, a, b));
            v.y = __saturatef(fmaf(v.y, a, b));
            v.z = __saturatef(fmaf(v.z, a, b));
            v.w = __saturatef(fmaf(v.w, a, b));
            __stcs(&xo[i], v);               // streaming store
        }
    }
}

extern "C" void kernel_launch(void* const* d_in, const int* in_sizes, int n_in,
                              void* d_out, int out_size) {
    const float* x = (const float*)d_in[0];
    float* out = (float*)d_out;
    int slices = out_size / N_PER;
    if (slices > MAX_SLICES) slices = MAX_SLICES;
    if (slices < 1) return;

    sample_kernel<<<slices, 256>>>(x);
    mega_kernel<<<slices * TPS, 256>>>(x, out);
}